// round 6
// baseline (speedup 1.0000x reference)
#include <cuda_runtime.h>

#define B 8
#define T_IN 512
#define D 384
#define VPR (D / 4)          // 96 float4s per row
#define T_MEL 3584
#define MEL_MAX 2048
#define CUMS (T_IN + 1)

// cumulative durations per batch
__device__ int g_cum[B * CUMS];

// ---------------- kernel 1: tiny scan per batch ----------------
__global__ void __launch_bounds__(128) scan_kernel(const int* __restrict__ dur,
                                                   float* __restrict__ dec_lens_out) {
    const int b = blockIdx.x;
    const int tid = threadIdx.x;
    __shared__ int wsum[4];

    int4 dv = ((const int4*)(dur + b * T_IN))[tid];
    int s0 = dv.x, s1 = s0 + dv.y, s2 = s1 + dv.z, s3 = s2 + dv.w;
    int v = s3;
    const int lane = tid & 31;
    #pragma unroll
    for (int off = 1; off < 32; off <<= 1) {
        int n = __shfl_up_sync(0xffffffffu, v, off);
        if (lane >= off) v += n;
    }
    if (lane == 31) wsum[tid >> 5] = v;
    __syncthreads();
    const int wid = tid >> 5;
    int woff = 0;
    #pragma unroll
    for (int w = 0; w < 3; w++) if (w < wid) woff += wsum[w];
    const int base = woff + v - s3;          // exclusive prefix of this int4

    int* cum = g_cum + b * CUMS;
    cum[4 * tid + 1] = base + s0;
    cum[4 * tid + 2] = base + s1;
    cum[4 * tid + 3] = base + s2;
    cum[4 * tid + 4] = base + s3;
    if (tid == 0) cum[0] = 0;
    if (tid == 127) {
        int total = base + s3;
        dec_lens_out[b] = (float)(total < MEL_MAX ? total : MEL_MAX);
    }
}

// ---------------- kernel 2: scatter (2 tokens/thread) + pitch + zero-fill ----------------
// blocks [0, 512):   scatter. block = 4 row-groups x 96 lanes, 8 tokens/block.
// blocks [512, 768): zero-fill, 64 rows per block, early exit if covered.
__global__ void __launch_bounds__(384) scatter_kernel(const float* __restrict__ enc,
                                                      const float* __restrict__ pitch,
                                                      float* __restrict__ enc_rep,
                                                      float* __restrict__ pitch_avg_out) {
    const int tid = threadIdx.x;
    const int lane = tid % VPR;
    const int rsub = tid / VPR;              // 0..3

    if (blockIdx.x < 512) {
        const int blk = blockIdx.x;
        const int b = blk >> 6;                        // 64 blocks per batch
        const int t0 = (blk & 63) * 8 + rsub * 2;      // first of 2 consecutive tokens
        const int* cum = g_cum + b * CUMS;

        // 3 independent cum loads + 2 independent row loads (chains overlap)
        const int c0 = __ldg(&cum[t0]);
        const int c1 = __ldg(&cum[t0 + 1]);
        const int c2 = __ldg(&cum[t0 + 2]);
        const float4* encb = (const float4*)enc + ((size_t)b * T_IN + t0) * VPR + lane;
        const float4 v0 = __ldg(encb);
        const float4 v1 = __ldg(encb + VPR);

        // contiguous output region [c0, c2): up to 14 independent stores
        const int e = c2 < MEL_MAX ? c2 : MEL_MAX;
        float4* outb = (float4*)enc_rep + (size_t)b * MEL_MAX * VPR + lane;
        #pragma unroll 4
        for (int m = c0; m < e; m++)
            outb[(size_t)m * VPR] = (m < c1) ? v0 : v1;

        // pitch average for both tokens (lane 0 only); unclamped boundaries
        if (lane == 0) {
            const float* p = pitch + (size_t)b * T_MEL;
            float sa = 0.f, ca = 0.f, sb = 0.f, cb = 0.f;
            for (int m = c0; m < c1; m++) {
                float pv = __ldg(&p[m]);
                sa += pv; if (pv != 0.0f) ca += 1.0f;
            }
            for (int m = c1; m < c2; m++) {
                float pv = __ldg(&p[m]);
                sb += pv; if (pv != 0.0f) cb += 1.0f;
            }
            pitch_avg_out[b * T_IN + t0]     = (ca != 0.0f) ? (sa / ca) : 0.0f;
            pitch_avg_out[b * T_IN + t0 + 1] = (cb != 0.0f) ? (sb / cb) : 0.0f;
        }
    } else {
        // ---- zero-fill rows [total, MEL_MAX) ----
        const int z = blockIdx.x - 512;
        const int b = z >> 5;                          // 32 blocks per batch
        const int rowbase = (z & 31) * 64;
        int total = __ldg(&g_cum[b * CUMS + T_IN]);
        if (total > MEL_MAX) total = MEL_MAX;
        if (rowbase + 64 <= total) return;

        const float4 zv = make_float4(0.f, 0.f, 0.f, 0.f);
        float4* outb = (float4*)enc_rep + (size_t)b * MEL_MAX * VPR + lane;
        #pragma unroll
        for (int i = 0; i < 16; i++) {
            const int m = rowbase + rsub + 4 * i;
            if (m >= total)
                outb[(size_t)m * VPR] = zv;
        }
    }
}

extern "C" void kernel_launch(void* const* d_in, const int* in_sizes, int n_in,
                              void* d_out, int out_size) {
    const float* enc_out = (const float*)d_in[0];   // [B, T_IN, D]
    const int* durations = (const int*)d_in[1];     // [B, T_IN]
    const float* pitch = (const float*)d_in[2];     // [B, 1, T_MEL]

    float* out = (float*)d_out;
    float* enc_rep = out;                               // B*MEL_MAX*D
    float* dec_lens = out + (size_t)B * MEL_MAX * D;    // B
    float* pitch_avg = dec_lens + B;                    // B*T_IN

    scan_kernel<<<B, 128>>>(durations, dec_lens);
    scatter_kernel<<<768, 384>>>(enc_out, pitch, enc_rep, pitch_avg);
}

// round 7
// speedup vs baseline: 1.0917x; 1.0917x over previous
#include <cuda_runtime.h>

#define B 8
#define T_IN 512
#define D 384
#define VPR (D / 4)          // 96 float4s per row
#define T_MEL 3584
#define MEL_MAX 2048
#define SCATTER_BLOCKS 1024  // 128 per batch x 4 tokens
#define ZF_BLOCKS 256        // 32 per batch x 64 rows
#define GRID (SCATTER_BLOCKS + ZF_BLOCKS)

__global__ void __launch_bounds__(384) fused_kernel(const float* __restrict__ enc,
                                                    const int* __restrict__ dur,
                                                    const float* __restrict__ pitch,
                                                    float* __restrict__ enc_rep,
                                                    float* __restrict__ dec_lens_out,
                                                    float* __restrict__ pitch_avg_out) {
    const int tid = threadIdx.x;
    const int lane = tid % VPR;
    const int rsub = tid / VPR;                 // 0..3
    const bool zf = blockIdx.x >= SCATTER_BLOCKS;
    const int zblk = blockIdx.x - SCATTER_BLOCKS;
    const int b = zf ? (zblk >> 5) : ((int)blockIdx.x >> 7);
    const int tloc = ((int)blockIdx.x & 127) * 4 + rsub;   // scatter token

    // kick off the enc row load BEFORE the scan — latency hides under it
    float4 v = make_float4(0.f, 0.f, 0.f, 0.f);
    if (!zf)
        v = __ldg((const float4*)enc + ((size_t)b * T_IN + tloc) * VPR + lane);

    __shared__ int cum[T_IN + 1];
    __shared__ int wsum[4];

    int s0 = 0, s1 = 0, s2 = 0, s3 = 0, pv = 0;
    if (tid < 128) {
        int4 dv = ((const int4*)(dur + b * T_IN))[tid];
        s0 = dv.x; s1 = s0 + dv.y; s2 = s1 + dv.z; s3 = s2 + dv.w;
        pv = s3;
        const int wl = tid & 31;
        #pragma unroll
        for (int off = 1; off < 32; off <<= 1) {
            int n = __shfl_up_sync(0xffffffffu, pv, off);
            if (wl >= off) pv += n;
        }
        if (wl == 31) wsum[tid >> 5] = pv;
    }
    __syncthreads();
    if (tid < 128) {
        const int wid = tid >> 5;
        int woff = 0;
        #pragma unroll
        for (int w = 0; w < 3; w++) if (w < wid) woff += wsum[w];
        const int base = woff + pv - s3;        // exclusive prefix of this int4
        cum[4 * tid + 1] = base + s0;
        cum[4 * tid + 2] = base + s1;
        cum[4 * tid + 3] = base + s2;
        cum[4 * tid + 4] = base + s3;
        if (tid == 0) cum[0] = 0;
    }
    __syncthreads();

    if (!zf) {
        // ---- producer scatter: token tloc -> rows [c0, c1) ----
        const int c0 = cum[tloc];
        const int c1 = cum[tloc + 1];
        const int e = c1 < MEL_MAX ? c1 : MEL_MAX;
        float4* outb = (float4*)enc_rep + (size_t)b * MEL_MAX * VPR + lane;
        #pragma unroll
        for (int k = 0; k < 7; k++) {           // durations in [0,8): max 7 reps
            const int m = c0 + k;
            if (m < e) outb[(size_t)m * VPR] = v;
        }
        // pitch average (N_FORMANTS=1), unclamped token range
        if (lane == 0) {
            const float* p = pitch + (size_t)b * T_MEL;
            float s = 0.0f, cnt = 0.0f;
            #pragma unroll
            for (int k = 0; k < 7; k++) {
                const int m = c0 + k;
                if (m < c1) {
                    float x = __ldg(&p[m]);
                    s += x;
                    if (x != 0.0f) cnt += 1.0f;
                }
            }
            pitch_avg_out[b * T_IN + tloc] = (cnt != 0.0f) ? (s / cnt) : 0.0f;
        }
    } else {
        // ---- zero-fill rows [total, MEL_MAX) ----
        int total = cum[T_IN];
        if (total > MEL_MAX) total = MEL_MAX;
        const int rowbase = (zblk & 31) * 64;
        if (tid == 0 && rowbase == 0)
            dec_lens_out[b] = (float)total;
        if (rowbase + 64 <= total) return;
        const float4 z = make_float4(0.f, 0.f, 0.f, 0.f);
        float4* outb = (float4*)enc_rep + (size_t)b * MEL_MAX * VPR + lane;
        #pragma unroll
        for (int i = 0; i < 16; i++) {
            const int m = rowbase + rsub + 4 * i;
            if (m >= total) outb[(size_t)m * VPR] = z;
        }
    }
}

extern "C" void kernel_launch(void* const* d_in, const int* in_sizes, int n_in,
                              void* d_out, int out_size) {
    const float* enc_out = (const float*)d_in[0];   // [B, T_IN, D]
    const int* durations = (const int*)d_in[1];     // [B, T_IN]
    const float* pitch = (const float*)d_in[2];     // [B, 1, T_MEL]

    float* out = (float*)d_out;
    float* enc_rep = out;                               // B*MEL_MAX*D
    float* dec_lens = out + (size_t)B * MEL_MAX * D;    // B
    float* pitch_avg = dec_lens + B;                    // B*T_IN

    fused_kernel<<<GRID, 384>>>(enc_out, durations, pitch,
                                enc_rep, dec_lens, pitch_avg);
}